// round 9
// baseline (speedup 1.0000x reference)
#include <cuda_runtime.h>
#include <math.h>

#define NN 10000
#define NE 40000
#define NG 128
#define VC 1584   // 32*48 kernel cols + 48 bias cols

// ---------------- scratch (static device globals; no runtime alloc) ----------
__device__ float g_a[NN * 32];
__device__ float g_e[NE * 32];
__device__ float g_s[NG * 16];
__device__ float g_v[NN * VC];      // 63.4 MB
__device__ float g_vs[NG * VC];     // 811 KB, per-graph state part of v
__device__ float g_wt[48 * VC];     // transposed kernel+bias
__device__ float g_agg[NN * 48];
__device__ float g_asum[NG * 32];
__device__ float g_esum[NG * 32];
__device__ float g_wcat1[32 * 192]; // [We rows 0:32 | We rows 32:64]
__device__ float g_wcat2[32 * 192]; // [We rows 80:112 | Ue]
__device__ float g_pa[NN * 192];    // a @ wcat1
__device__ float g_ew[NE * 192];    // e @ wcat2
__device__ float g_s3[NG * 96];     // s @ We rows 64:80
__device__ float g_agw[NN * 96];    // agg @ Wn
__device__ float g_au[NN * 96];     // a @ Un

__device__ __forceinline__ float sigm(float x) { return 1.f / (1.f + expf(-x)); }

__device__ __forceinline__ unsigned f2tf(float f) {
    unsigned u;
    asm("cvt.rna.tf32.f32 %0, %1;" : "=r"(u) : "f"(f));
    return u;
}
__device__ __forceinline__ void mma_tf32(float c[4],
                                         unsigned a0, unsigned a1,
                                         unsigned a2, unsigned a3,
                                         unsigned b0, unsigned b1) {
    asm volatile(
        "mma.sync.aligned.m16n8k8.row.col.f32.tf32.tf32.f32 "
        "{%0,%1,%2,%3}, {%4,%5,%6,%7}, {%8,%9}, {%0,%1,%2,%3};"
        : "+f"(c[0]), "+f"(c[1]), "+f"(c[2]), "+f"(c[3])
        : "r"(a0), "r"(a1), "r"(a2), "r"(a3), "r"(b0), "r"(b1));
}

// ---------------- weight prep ------------------------------------------------
__global__ void build_weights_kernel(const float* __restrict__ kern,
                                     const float* __restrict__ bias,
                                     const float* __restrict__ We,
                                     const float* __restrict__ Ue,
                                     float* __restrict__ wt,
                                     float* __restrict__ wcat1,
                                     float* __restrict__ wcat2) {
    int idx = blockIdx.x * blockDim.x + threadIdx.x;
    if (idx < 48 * VC) {
        int j = idx / VC, ki = idx % VC;
        wt[idx] = (ki < 1536) ? kern[ki * 48 + j] : bias[(ki - 1536) * 48 + j];
    }
    if (idx < 32 * 192) {
        int k = idx / 192, c = idx % 192;
        wcat1[idx] = (c < 96) ? We[k * 96 + c] : We[(32 + k) * 96 + (c - 96)];
        wcat2[idx] = (c < 96) ? We[(80 + k) * 96 + c] : Ue[k * 96 + (c - 96)];
    }
}

// ---------------- zero scratch ------------------------------------------------
__global__ void zero_kernel(float* __restrict__ agg, float* __restrict__ as,
                            float* __restrict__ es) {
    int i = blockIdx.x * blockDim.x + threadIdx.x;
    if (i < NN * 48) agg[i] = 0.f;
    if (i < NG * 32) { as[i] = 0.f; es[i] = 0.f; }
}

// ---------------- small-K dense GEMM: Y(MxNC) = X(MxK) @ W(KxNC) -------------
template<int K, int NC, int RT>
__global__ __launch_bounds__(NC)
void gemm_kernel(const float* __restrict__ X, const float* __restrict__ W,
                 float* __restrict__ Y, int M) {
    __shared__ float sW[K * NC];
    __shared__ __align__(16) float sx[RT * K];
    int tid = threadIdx.x;
    int base = blockIdx.x * RT;
#pragma unroll
    for (int k = 0; k < K; k++) sW[k * NC + tid] = W[k * NC + tid];
    int lim = (M - base) * K;
    for (int i = tid; i < RT * K; i += NC)
        sx[i] = (i < lim) ? X[(size_t)base * K + i] : 0.f;
    __syncthreads();

    float acc[RT];
#pragma unroll
    for (int r = 0; r < RT; r++) acc[r] = 0.f;
    const float4* sx4 = (const float4*)sx;
#pragma unroll
    for (int k4 = 0; k4 < K / 4; k4++) {
        float w0 = sW[(4 * k4 + 0) * NC + tid];
        float w1 = sW[(4 * k4 + 1) * NC + tid];
        float w2 = sW[(4 * k4 + 2) * NC + tid];
        float w3 = sW[(4 * k4 + 3) * NC + tid];
#pragma unroll
        for (int r = 0; r < RT; r++) {
            float4 xv = sx4[r * (K / 4) + k4];
            acc[r] += w0 * xv.x; acc[r] += w1 * xv.y;
            acc[r] += w2 * xv.z; acc[r] += w3 * xv.w;
        }
    }
#pragma unroll
    for (int r = 0; r < RT; r++) {
        int row = base + r;
        if (row < M) Y[(size_t)row * NC + tid] = acc[r];
    }
}

// ---------------- edge GRU finalize (pure elementwise) -----------------------
__global__ __launch_bounds__(256)
void edge_finalize_kernel(const float* __restrict__ pa,
                          const float* __restrict__ ew,
                          const float* __restrict__ s3,
                          const float* __restrict__ e_in,
                          const int* __restrict__ pair,
                          const int* __restrict__ bgi,
                          const float* __restrict__ bin,
                          const float* __restrict__ brec,
                          float* __restrict__ e_out,
                          float* __restrict__ esum) {
    int idx = blockIdx.x * blockDim.x + threadIdx.x;
    if (idx >= NE * 32) return;
    int e = idx >> 5, j = idx & 31;
    int src = pair[2 * e], dst = pair[2 * e + 1], g = bgi[e];
    const float* pA = pa + (size_t)src * 192;
    const float* pB = pa + (size_t)dst * 192 + 96;
    const float* pS = s3 + g * 96;
    const float* pE = ew + (size_t)e * 192;
    float xz = pA[j]      + pB[j]      + pS[j]      + pE[j]      + bin[j];
    float xr = pA[32 + j] + pB[32 + j] + pS[32 + j] + pE[32 + j] + bin[32 + j];
    float xh = pA[64 + j] + pB[64 + j] + pS[64 + j] + pE[64 + j] + bin[64 + j];
    float hz = pE[96 + j]  + brec[j];
    float hr = pE[128 + j] + brec[32 + j];
    float hh = pE[160 + j] + brec[64 + j];
    float h  = e_in[(size_t)e * 32 + j];
    float z  = sigm(xz + hz);
    float r  = sigm(xr + hr);
    float hc = tanhf(xh + r * hh);
    float val = z * h + (1.f - z) * hc;
    e_out[(size_t)e * 32 + j] = val;
    atomicAdd(&esum[g * 32 + j], val);
}

// ---------------- node GRU finalize ------------------------------------------
__global__ __launch_bounds__(256)
void node_finalize_kernel(const float* __restrict__ agw,
                          const float* __restrict__ au,
                          const float* __restrict__ a_in,
                          const int* __restrict__ agi,
                          const float* __restrict__ bin,
                          const float* __restrict__ brec,
                          float* __restrict__ a_out,
                          float* __restrict__ asum) {
    int idx = blockIdx.x * blockDim.x + threadIdx.x;
    if (idx >= NN * 32) return;
    int n = idx >> 5, j = idx & 31;
    const float* pX = agw + (size_t)n * 96;
    const float* pH = au  + (size_t)n * 96;
    float xz = pX[j]      + bin[j];
    float xr = pX[32 + j] + bin[32 + j];
    float xh = pX[64 + j] + bin[64 + j];
    float hz = pH[j]      + brec[j];
    float hr = pH[32 + j] + brec[32 + j];
    float hh = pH[64 + j] + brec[64 + j];
    float h  = a_in[(size_t)n * 32 + j];
    float z  = sigm(xz + hz);
    float r  = sigm(xr + hr);
    float hc = tanhf(xh + r * hh);
    float val = z * h + (1.f - z) * hc;
    a_out[(size_t)n * 32 + j] = val;
    atomicAdd(&asum[agi[n] * 32 + j], val);
}

// ---------------- vs[g][c] = sum_j wt[32+j][c] * s[g][j]  (state part) -------
__global__ __launch_bounds__(256)
void vs_kernel(const float* __restrict__ s, const float* __restrict__ wt,
               float* __restrict__ vs) {
    __shared__ float ss[16];
    int g = blockIdx.y;
    int c = blockIdx.x * 256 + threadIdx.x;
    if (threadIdx.x < 16) ss[threadIdx.x] = s[g * 16 + threadIdx.x];
    __syncthreads();
    if (c >= VC) return;
    float acc = 0.f;
#pragma unroll
    for (int j = 0; j < 16; j++) acc += ss[j] * wt[(32 + j) * VC + c];
    vs[(size_t)g * VC + c] = acc;
}

// ---------------- v = a @ Wt_a (tf32 tensor cores) + vs[agi] gather ----------
// Block: 256 thr = 8 warps as 4(m) x 2(n). Block tile: 64 rows x 128 cols.
__global__ __launch_bounds__(256)
void compute_v_mma_kernel(const float* __restrict__ a,
                          const int* __restrict__ agi,
                          const float* __restrict__ wt,
                          const float* __restrict__ vs,
                          float* __restrict__ v) {
    __shared__ unsigned sA[64 * 33];
    __shared__ unsigned sB[32 * 132];
    __shared__ int s_gi[64];
    int m0 = blockIdx.y * 64;
    int n0 = blockIdx.x * 128;
    int tid = threadIdx.x;

    for (int i = tid; i < 64 * 32; i += 256) {
        int r = i >> 5, k = i & 31;
        float val = (m0 + r < NN) ? a[(size_t)(m0 + r) * 32 + k] : 0.f;
        sA[r * 33 + k] = f2tf(val);
    }
    for (int i = tid; i < 32 * 128; i += 256) {
        int k = i >> 7, n = i & 127;
        float val = (n0 + n < VC) ? wt[(size_t)k * VC + n0 + n] : 0.f;
        sB[k * 132 + n] = f2tf(val);
    }
    if (tid < 64) s_gi[tid] = (m0 + tid < NN) ? agi[m0 + tid] : 0;
    __syncthreads();

    int wid = tid >> 5, lane = tid & 31;
    int wm = wid & 3, wn = wid >> 2;     // warp tile: rows wm*16, cols wn*64
    int lq = lane >> 2, lr = lane & 3;   // quad row / in-quad col

    float c[8][4];
#pragma unroll
    for (int nf = 0; nf < 8; nf++)
#pragma unroll
        for (int i = 0; i < 4; i++) c[nf][i] = 0.f;

#pragma unroll
    for (int ks = 0; ks < 4; ks++) {
        int ar = wm * 16 + lq;
        int ac = ks * 8 + lr;
        unsigned a0 = sA[ar * 33 + ac];
        unsigned a1 = sA[(ar + 8) * 33 + ac];
        unsigned a2 = sA[ar * 33 + ac + 4];
        unsigned a3 = sA[(ar + 8) * 33 + ac + 4];
#pragma unroll
        for (int nf = 0; nf < 8; nf++) {
            int bn = wn * 64 + nf * 8 + lq;
            unsigned b0 = sB[(ks * 8 + lr) * 132 + bn];
            unsigned b1 = sB[(ks * 8 + 4 + lr) * 132 + bn];
            mma_tf32(c[nf], a0, a1, a2, a3, b0, b1);
        }
    }

    int row_l = wm * 16 + lq;
    int r0 = m0 + row_l, r1 = r0 + 8;
    int gi0 = s_gi[row_l], gi1 = s_gi[row_l + 8];
    int cb = n0 + wn * 64 + lr * 2;
#pragma unroll
    for (int nf = 0; nf < 8; nf++) {
        int col = cb + nf * 8;
        if (col >= VC) continue;
        if (r0 < NN) {
            float2 w = *(const float2*)&vs[(size_t)gi0 * VC + col];
            float2 o = make_float2(c[nf][0] + w.x, c[nf][1] + w.y);
            *(float2*)&v[(size_t)r0 * VC + col] = o;
        }
        if (r1 < NN) {
            float2 w = *(const float2*)&vs[(size_t)gi1 * VC + col];
            float2 o = make_float2(c[nf][2] + w.x, c[nf][3] + w.y);
            *(float2*)&v[(size_t)r1 * VC + col] = o;
        }
    }
}

// ---------------- per-edge message + scatter-add by src (src-run dedup) ------
#define EPW 8
__global__ __launch_bounds__(256)
void scatter_kernel(const float* __restrict__ e_feat,
                    const int* __restrict__ pair,
                    const float* __restrict__ v,
                    float* __restrict__ agg) {
    int lane = threadIdx.x & 31;
    int warp = (blockIdx.x * blockDim.x + threadIdx.x) >> 5;
    int e0 = warp * EPW;
    if (e0 >= NE) return;
    int eend = min(e0 + EPW, NE);
    int cur_src = __ldg(&pair[2 * e0]);
    float acc0 = 0.f, acc1 = 0.f;
    for (int e = e0; e < eend; e++) {
        int src = __ldg(&pair[2 * e]);
        int dst = __ldg(&pair[2 * e + 1]);
        if (src != cur_src) {
            atomicAdd(&agg[cur_src * 48 + lane], acc0);
            if (lane < 16) atomicAdd(&agg[cur_src * 48 + 32 + lane], acc1);
            acc0 = 0.f; acc1 = 0.f; cur_src = src;
        }
        const float* vp = v + (size_t)dst * VC;
        float ev = __ldg(&e_feat[(size_t)e * 32 + lane]);
        acc0 += __ldg(&vp[1536 + lane]);
        if (lane < 16) acc1 += __ldg(&vp[1568 + lane]);
#pragma unroll
        for (int k = 0; k < 32; k++) {
            float ek = __shfl_sync(0xffffffffu, ev, k);
            acc0 += ek * __ldg(&vp[k * 48 + lane]);
            if (lane < 16) acc1 += ek * __ldg(&vp[k * 48 + 32 + lane]);
        }
    }
    atomicAdd(&agg[cur_src * 48 + lane], acc0);
    if (lane < 16) atomicAdd(&agg[cur_src * 48 + 32 + lane], acc1);
}

// ---------------- state GRU: s = GRU([asum, esum, s], s) ---------------------
__global__ void state_gru_kernel(
    const float* __restrict__ asum, const float* __restrict__ esum,
    const float* __restrict__ s_in,
    const float* __restrict__ Ws, const float* __restrict__ Us,
    const float* __restrict__ bsin, const float* __restrict__ bsrec,
    float* __restrict__ s_out) {
    __shared__ float sx[80];
    __shared__ float shh[16];
    __shared__ float sxw[48];
    __shared__ float shu[48];
    int g = blockIdx.x;
    int c = threadIdx.x;  // 80
    if (c < 32)      sx[c] = asum[g * 32 + c];
    else if (c < 64) sx[c] = esum[g * 32 + (c - 32)];
    else             sx[c] = s_in[g * 16 + (c - 64)];
    if (c < 16) shh[c] = s_in[g * 16 + c];
    __syncthreads();
    if (c < 48) {
        float xw = bsin[c], hu = bsrec[c];
        for (int k = 0; k < 80; k++) xw += sx[k] * Ws[k * 48 + c];
        for (int k = 0; k < 16; k++) hu += shh[k] * Us[k * 48 + c];
        sxw[c] = xw; shu[c] = hu;
    }
    __syncthreads();
    if (c < 16) {
        float z = sigm(sxw[c] + shu[c]);
        float r = sigm(sxw[16 + c] + shu[16 + c]);
        float hc = tanhf(sxw[32 + c] + r * shu[32 + c]);
        s_out[g * 16 + c] = z * shh[c] + (1.f - z) * hc;
    }
}

// ---------------- host orchestration -----------------------------------------
extern "C" void kernel_launch(void* const* d_in, const int* in_sizes, int n_in,
                              void* d_out, int out_size) {
    const float* a0    = (const float*)d_in[0];
    const float* e0    = (const float*)d_in[1];
    const float* s0    = (const float*)d_in[2];
    const int*   pair  = (const int*)d_in[3];
    const int*   agi   = (const int*)d_in[4];
    const int*   bgi   = (const int*)d_in[5];
    const float* kern  = (const float*)d_in[6];
    const float* bias  = (const float*)d_in[7];
    const float* We    = (const float*)d_in[8];
    const float* Ue    = (const float*)d_in[9];
    const float* bein  = (const float*)d_in[10];
    const float* berec = (const float*)d_in[11];
    const float* Wn    = (const float*)d_in[12];
    const float* Un    = (const float*)d_in[13];
    const float* bnin  = (const float*)d_in[14];
    const float* bnrec = (const float*)d_in[15];
    const float* Ws    = (const float*)d_in[16];
    const float* Us    = (const float*)d_in[17];
    const float* bsin  = (const float*)d_in[18];
    const float* bsrec = (const float*)d_in[19];
    float* out = (float*)d_out;

    float *ga, *ge, *gs, *gv, *gvs, *gwt, *gagg, *gas, *ges;
    float *gw1, *gw2, *gpa, *gew, *gs3, *gagw, *gau;
    cudaGetSymbolAddress((void**)&ga,   g_a);
    cudaGetSymbolAddress((void**)&ge,   g_e);
    cudaGetSymbolAddress((void**)&gs,   g_s);
    cudaGetSymbolAddress((void**)&gv,   g_v);
    cudaGetSymbolAddress((void**)&gvs,  g_vs);
    cudaGetSymbolAddress((void**)&gwt,  g_wt);
    cudaGetSymbolAddress((void**)&gagg, g_agg);
    cudaGetSymbolAddress((void**)&gas,  g_asum);
    cudaGetSymbolAddress((void**)&ges,  g_esum);
    cudaGetSymbolAddress((void**)&gw1,  g_wcat1);
    cudaGetSymbolAddress((void**)&gw2,  g_wcat2);
    cudaGetSymbolAddress((void**)&gpa,  g_pa);
    cudaGetSymbolAddress((void**)&gew,  g_ew);
    cudaGetSymbolAddress((void**)&gs3,  g_s3);
    cudaGetSymbolAddress((void**)&gagw, g_agw);
    cudaGetSymbolAddress((void**)&gau,  g_au);

    static bool s_init = false;
    static cudaStream_t st1, st2;
    static cudaEvent_t ev0[2], evZ[2], evP[2], evE[2], evU[2];
    if (!s_init) {
        cudaStreamCreateWithFlags(&st1, cudaStreamNonBlocking);
        cudaStreamCreateWithFlags(&st2, cudaStreamNonBlocking);
        for (int i = 0; i < 2; i++) {
            cudaEventCreateWithFlags(&ev0[i], cudaEventDisableTiming);
            cudaEventCreateWithFlags(&evZ[i], cudaEventDisableTiming);
            cudaEventCreateWithFlags(&evP[i], cudaEventDisableTiming);
            cudaEventCreateWithFlags(&evE[i], cudaEventDisableTiming);
            cudaEventCreateWithFlags(&evU[i], cudaEventDisableTiming);
        }
        s_init = true;
    }

    build_weights_kernel<<<(48 * VC + 255) / 256, 256>>>(kern, bias, We, Ue,
                                                         gwt, gw1, gw2);

    float* oa[2] = {ga, out};
    float* oe[2] = {ge, out + NN * 32};
    float* os[2] = {gs, out + NN * 32 + NE * 32};
    const float* ia = a0;
    const float* ie = e0;
    const float* is_ = s0;

    for (int step = 0; step < 2; step++) {
        cudaEventRecord(ev0[step], 0);

        // main stream (critical path): vs then tf32 v-GEMM
        vs_kernel<<<dim3((VC + 255) / 256, NG), 256>>>(is_, gwt, gvs);
        compute_v_mma_kernel<<<dim3((VC + 127) / 128, (NN + 63) / 64), 256>>>(
            ia, agi, gwt, gvs, gv);

        // stream 2: zero scratch, pa GEMM, Un GEMM
        cudaStreamWaitEvent(st2, ev0[step], 0);
        zero_kernel<<<(NN * 48 + 255) / 256, 256, 0, st2>>>(gagg, gas, ges);
        cudaEventRecord(evZ[step], st2);
        gemm_kernel<32, 192, 16><<<NN / 16, 192, 0, st2>>>(ia, gw1, gpa, NN);
        cudaEventRecord(evP[step], st2);
        gemm_kernel<32, 96, 16><<<NN / 16, 96, 0, st2>>>(ia, Un, gau, NN);
        cudaEventRecord(evU[step], st2);

        // stream 1: ew + s3 GEMMs, then finalize (needs pa + zeroed esum)
        cudaStreamWaitEvent(st1, ev0[step], 0);
        gemm_kernel<32, 192, 16><<<NE / 16, 192, 0, st1>>>(ie, gw2, gew, NE);
        gemm_kernel<16, 96, 16><<<NG / 16, 96, 0, st1>>>(is_, We + 64 * 96, gs3, NG);
        cudaStreamWaitEvent(st1, evZ[step], 0);
        cudaStreamWaitEvent(st1, evP[step], 0);
        edge_finalize_kernel<<<(NE * 32 + 255) / 256, 256, 0, st1>>>(
            gpa, gew, gs3, ie, pair, bgi, bein, berec, oe[step], ges);
        cudaEventRecord(evE[step], st1);

        // join on main: scatter needs v (main) + e_out (st1)
        cudaStreamWaitEvent(0, evE[step], 0);
        scatter_kernel<<<(NE / EPW + 7) / 8, 256>>>(oe[step], pair, gv, gagg);

        gemm_kernel<48, 96, 16><<<NN / 16, 96>>>(gagg, Wn, gagw, NN);
        cudaStreamWaitEvent(0, evU[step], 0);
        node_finalize_kernel<<<(NN * 32 + 255) / 256, 256>>>(
            gagw, gau, ia, agi, bnin, bnrec, oa[step], gas);

        state_gru_kernel<<<NG, 80>>>(gas, ges, is_, Ws, Us, bsin, bsrec, os[step]);

        ia = oa[step]; ie = oe[step]; is_ = os[step];
    }
}